// round 1
// baseline (speedup 1.0000x reference)
#include <cuda_runtime.h>

// ---------------------------------------------------------------------------
// PartBasedGraphCNN: conv3x3(3->32)+relu+pool2 -> grid-GCN(32->64) -> FC1 -> FC2
// All fp32, packed f32x2 FMA. 4 kernels, __device__ scratch, no atomics.
// ---------------------------------------------------------------------------

#define K_FC 262144  // 4096 nodes * 64 feats

__device__ float d_pool_buf[32 * 32 * 64 * 64];     // [B][32][64][64]  16.8 MB
__device__ float d_g_buf[32u * 4096u * 64u];        // [B][N][64]       33.6 MB
__device__ float d_part_buf[512 * 32 * 128];        // [chunk][B][128]   8.4 MB

__device__ __forceinline__ void fma2(float2 &d, const float2 a, const float2 b) {
    asm("fma.rn.f32x2 %0, %1, %2, %0;"
        : "+l"(*reinterpret_cast<unsigned long long *>(&d))
        : "l"(*reinterpret_cast<const unsigned long long *>(&a)),
          "l"(*reinterpret_cast<const unsigned long long *>(&b)));
}

// ---------------------------------------------------------------------------
// Kernel 1: conv 3x3 SAME + bias + relu + maxpool 2x2
// grid (16 tiles, 32 batch), block 256 = 16x16 pooled pixels (32x32 pre-pool)
// ---------------------------------------------------------------------------
__global__ void __launch_bounds__(256) conv_pool_kernel(
    const float *__restrict__ x, const float *__restrict__ cw,
    const float *__restrict__ cb)
{
    __shared__ float sin_[3][34][34];
    __shared__ float wp[27 * 32];  // [tap][co], co pairs contiguous -> float2
    __shared__ float bb[32];

    int t = threadIdx.x;
    int b = blockIdx.y;
    int tpy = (blockIdx.x >> 2) * 16, tpx = (blockIdx.x & 3) * 16;

    for (int i = t; i < 864; i += 256) {
        int co = i / 27, rem = i % 27;  // global layout co*27 + (ci*9+ky*3+kx)
        wp[rem * 32 + co] = cw[i];
    }
    if (t < 32) bb[t] = cb[t];

    int oy = 2 * tpy - 1, ox = 2 * tpx - 1;
    for (int i = t; i < 3 * 34 * 34; i += 256) {
        int ci = i / 1156, rem = i % 1156, iy = rem / 34, ix = rem % 34;
        int gy = oy + iy, gx = ox + ix;
        float v = 0.f;
        if (gy >= 0 && gy < 128 && gx >= 0 && gx < 128)
            v = x[((b * 3 + ci) * 128 + gy) * 128 + gx];
        sin_[ci][iy][ix] = v;
    }
    __syncthreads();

    int py = t >> 4, px = t & 15;
    float in[3][4][4];
#pragma unroll
    for (int ci = 0; ci < 3; ci++)
#pragma unroll
        for (int r = 0; r < 4; r++)
#pragma unroll
            for (int c = 0; c < 4; c++)
                in[ci][r][c] = sin_[ci][2 * py + r][2 * px + c];

    const float2 *wp2 = reinterpret_cast<const float2 *>(wp);
    int gy = tpy + py, gx = tpx + px;
    float *outb = d_pool_buf + (size_t)b * 131072;

#pragma unroll
    for (int g = 0; g < 4; g++) {  // 8 output channels per group (4 pairs)
        float2 acc[2][2][4];
#pragma unroll
        for (int dy = 0; dy < 2; dy++)
#pragma unroll
            for (int dx = 0; dx < 2; dx++)
#pragma unroll
                for (int p = 0; p < 4; p++) acc[dy][dx][p] = make_float2(0.f, 0.f);

#pragma unroll
        for (int ci = 0; ci < 3; ci++)
#pragma unroll
            for (int ky = 0; ky < 3; ky++)
#pragma unroll
                for (int kx = 0; kx < 3; kx++) {
                    int tap = ci * 9 + ky * 3 + kx;
                    float2 w0 = wp2[tap * 16 + g * 4 + 0];
                    float2 w1 = wp2[tap * 16 + g * 4 + 1];
                    float2 w2 = wp2[tap * 16 + g * 4 + 2];
                    float2 w3 = wp2[tap * 16 + g * 4 + 3];
#pragma unroll
                    for (int dy = 0; dy < 2; dy++)
#pragma unroll
                        for (int dx = 0; dx < 2; dx++) {
                            float iv = in[ci][dy + ky][dx + kx];
                            float2 iv2 = make_float2(iv, iv);
                            fma2(acc[dy][dx][0], iv2, w0);
                            fma2(acc[dy][dx][1], iv2, w1);
                            fma2(acc[dy][dx][2], iv2, w2);
                            fma2(acc[dy][dx][3], iv2, w3);
                        }
                }
#pragma unroll
        for (int p = 0; p < 4; p++) {
            int co = g * 8 + p * 2;
            float mx = fmaxf(fmaxf(acc[0][0][p].x, acc[0][1][p].x),
                             fmaxf(acc[1][0][p].x, acc[1][1][p].x));
            float my = fmaxf(fmaxf(acc[0][0][p].y, acc[0][1][p].y),
                             fmaxf(acc[1][0][p].y, acc[1][1][p].y));
            mx = fmaxf(mx + bb[co], 0.f);
            my = fmaxf(my + bb[co + 1], 0.f);
            outb[(co * 64 + gy) * 64 + gx] = mx;
            outb[((co + 1) * 64 + gy) * 64 + gx] = my;
        }
    }
}

// ---------------------------------------------------------------------------
// Kernel 2: GCN. Stencil on raw-view 32-dim node feats (agg commutes with W),
// then [512n x 32] @ [32 x 64] + bias + relu. grid (8 rowgroups, 32 batch).
// ---------------------------------------------------------------------------
__device__ __forceinline__ float dinvf(int r, int c) {
    int deg = 1 + (r > 0) + (r < 63) + (c > 0) + (c < 63);
    return rsqrtf((float)deg);
}

__global__ void __launch_bounds__(256) gcn_kernel(
    const float *__restrict__ gw, const float *__restrict__ gb)
{
    extern __shared__ float sm[];
    float *aggx = sm;            // [512][36] padded
    float *wg = sm + 512 * 36;   // [32][64]
    float *bg = wg + 2048;       // [64]

    int t = threadIdx.x, b = blockIdx.y;
    int node0 = blockIdx.x * 512;

    for (int i = t; i < 2048; i += 256) wg[i] = gw[i];
    if (t < 64) bg[t] = gb[t];

    const float *nf = d_pool_buf + (size_t)b * 131072;  // node feats [4096][32]
    int q = t & 7, ns = t >> 3;
#pragma unroll 4
    for (int i = 0; i < 16; i++) {
        int nl = ns + 32 * i;
        int n = node0 + nl;
        int r = n >> 6, c = n & 63;
        float dn = dinvf(r, c);
        const float4 *base = reinterpret_cast<const float4 *>(nf) + n * 8 + q;
        float4 v = __ldg(base);
        float4 a;
        a.x = dn * v.x; a.y = dn * v.y; a.z = dn * v.z; a.w = dn * v.w;
        if (r > 0) {
            float s = dinvf(r - 1, c); float4 u = __ldg(base - 512);
            a.x += s * u.x; a.y += s * u.y; a.z += s * u.z; a.w += s * u.w;
        }
        if (r < 63) {
            float s = dinvf(r + 1, c); float4 u = __ldg(base + 512);
            a.x += s * u.x; a.y += s * u.y; a.z += s * u.z; a.w += s * u.w;
        }
        if (c > 0) {
            float s = dinvf(r, c - 1); float4 u = __ldg(base - 8);
            a.x += s * u.x; a.y += s * u.y; a.z += s * u.z; a.w += s * u.w;
        }
        if (c < 63) {
            float s = dinvf(r, c + 1); float4 u = __ldg(base + 8);
            a.x += s * u.x; a.y += s * u.y; a.z += s * u.z; a.w += s * u.w;
        }
        a.x *= dn; a.y *= dn; a.z *= dn; a.w *= dn;
        *reinterpret_cast<float4 *>(&aggx[nl * 36 + q * 4]) = a;
    }
    __syncthreads();

    // GEMM: thread tile = 8 nodes x 8 outs (4 output-pairs), 2 iterations
    int ot = t & 7, ng = t >> 3;
    const float4 *wg4 = reinterpret_cast<const float4 *>(wg);
    float *gout = d_g_buf + (size_t)b * 262144;
#pragma unroll
    for (int it = 0; it < 2; it++) {
        int nb = (it * 32 + ng) * 8;
        float2 acc[8][4];
#pragma unroll
        for (int i = 0; i < 8; i++)
#pragma unroll
            for (int p = 0; p < 4; p++) acc[i][p] = make_float2(0.f, 0.f);

#pragma unroll 4
        for (int f = 0; f < 32; f++) {
            float4 wA = wg4[f * 16 + ot * 2];
            float4 wB = wg4[f * 16 + ot * 2 + 1];
            float2 p0 = make_float2(wA.x, wA.y), p1 = make_float2(wA.z, wA.w);
            float2 p2 = make_float2(wB.x, wB.y), p3 = make_float2(wB.z, wB.w);
#pragma unroll
            for (int i = 0; i < 8; i++) {
                float av = aggx[(nb + i) * 36 + f];
                float2 ad = make_float2(av, av);
                fma2(acc[i][0], ad, p0);
                fma2(acc[i][1], ad, p1);
                fma2(acc[i][2], ad, p2);
                fma2(acc[i][3], ad, p3);
            }
        }
#pragma unroll
        for (int i = 0; i < 8; i++) {
            float2 *op = reinterpret_cast<float2 *>(
                gout + (size_t)(node0 + nb + i) * 64 + ot * 8);
#pragma unroll
            for (int p = 0; p < 4; p++) {
                float2 v;
                v.x = fmaxf(acc[i][p].x + bg[ot * 8 + 2 * p], 0.f);
                v.y = fmaxf(acc[i][p].y + bg[ot * 8 + 2 * p + 1], 0.f);
                op[p] = v;
            }
        }
    }
}

// ---------------------------------------------------------------------------
// Kernel 3: FC1 split-K. 512 chunks x Kc=512 (4 sub-chunks of 128).
// C tile 32x128 per chunk; thread tile = 8 batches (4 f32x2) x 4 cols.
// W staged transposed [k][j] stride 130 (conflict-free transpose stores).
// ---------------------------------------------------------------------------
__global__ void __launch_bounds__(128) fc1_kernel(const float *__restrict__ w1)
{
    extern __shared__ float sm[];
    float *Ws = sm;               // [128][130]
    float *Gs = sm + 128 * 130;   // [128][34]
    const float *g = d_g_buf;     // flat [32][262144]

    int t = threadIdx.x, jt = t & 31, mt = t >> 5;
    int k0 = blockIdx.x * 512;

    float2 acc[4][4];
#pragma unroll
    for (int i = 0; i < 4; i++)
#pragma unroll
        for (int jj = 0; jj < 4; jj++) acc[i][jj] = make_float2(0.f, 0.f);

    for (int s = 0; s < 4; s++) {
        int ks = k0 + s * 128;
        __syncthreads();
#pragma unroll 4
        for (int i = 0; i < 64; i++) {  // W: 128j x 128k
            int idx = i * 128 + t;
            int j = idx >> 6, kp = idx & 63;
            float2 v = *reinterpret_cast<const float2 *>(
                w1 + (size_t)j * K_FC + ks + kp * 2);
            Ws[(kp * 2) * 130 + j] = v.x;
            Ws[(kp * 2 + 1) * 130 + j] = v.y;
        }
#pragma unroll 4
        for (int i = 0; i < 16; i++) {  // G: 32b x 128k
            int idx = i * 128 + t;
            int bb = idx >> 6, kp = idx & 63;
            float2 v = *reinterpret_cast<const float2 *>(
                g + (size_t)bb * K_FC + ks + kp * 2);
            Gs[(kp * 2) * 34 + bb] = v.x;
            Gs[(kp * 2 + 1) * 34 + bb] = v.y;
        }
        __syncthreads();
#pragma unroll 2
        for (int k = 0; k < 128; k++) {
            float2 gm[4];
#pragma unroll
            for (int i = 0; i < 4; i++)
                gm[i] = *reinterpret_cast<const float2 *>(
                    &Gs[k * 34 + mt * 8 + 2 * i]);
            float2 wd[4];
#pragma unroll
            for (int jj = 0; jj < 4; jj++) {
                float w = Ws[k * 130 + jt * 4 + jj];
                wd[jj] = make_float2(w, w);
            }
#pragma unroll
            for (int i = 0; i < 4; i++)
#pragma unroll
                for (int jj = 0; jj < 4; jj++) fma2(acc[i][jj], gm[i], wd[jj]);
        }
    }

    float *pp = d_part_buf + (size_t)blockIdx.x * 4096;
#pragma unroll
    for (int i = 0; i < 4; i++) {
        int b0 = mt * 8 + 2 * i;
#pragma unroll
        for (int jj = 0; jj < 4; jj++) {
            pp[b0 * 128 + jt * 4 + jj] = acc[i][jj].x;
            pp[(b0 + 1) * 128 + jt * 4 + jj] = acc[i][jj].y;
        }
    }
}

// ---------------------------------------------------------------------------
// Kernel 4: reduce 512 partials -> relu(f1 + b1) -> FC2 (101x128) -> out
// grid 32 (one block per batch), 1024 threads (8 reduce groups x 128 j)
// ---------------------------------------------------------------------------
__global__ void __launch_bounds__(1024) reduce_fc2_kernel(
    const float *__restrict__ f1b, const float *__restrict__ w2,
    const float *__restrict__ b2, float *__restrict__ out)
{
    __shared__ float red[8][128];
    __shared__ float f1s[128];
    int t = threadIdx.x, b = blockIdx.x;
    int j = t & 127, cg = t >> 7;

    const float *pp = d_part_buf + b * 128 + j;
    float s = 0.f;
#pragma unroll 8
    for (int c = cg; c < 512; c += 8) s += pp[(size_t)c * 4096];
    red[cg][j] = s;
    __syncthreads();

    if (cg == 0) {
        float v = red[0][j];
#pragma unroll
        for (int u = 1; u < 8; u++) v += red[u][j];
        f1s[j] = fmaxf(v + f1b[j], 0.f);
    }
    __syncthreads();

    if (t < 101) {
        float acc = b2[t];
        const float *wr = w2 + t * 128;
#pragma unroll 8
        for (int jj = 0; jj < 128; jj++) acc = fmaf(f1s[jj], __ldg(&wr[jj]), acc);
        out[b * 101 + t] = acc;
    }
}

// ---------------------------------------------------------------------------
extern "C" void kernel_launch(void *const *d_in, const int *in_sizes, int n_in,
                              void *d_out, int out_size)
{
    (void)in_sizes; (void)n_in; (void)out_size;
    const float *x  = (const float *)d_in[0];
    const float *cw = (const float *)d_in[1];
    const float *cb = (const float *)d_in[2];
    const float *gw = (const float *)d_in[3];
    const float *gb = (const float *)d_in[4];
    const float *w1 = (const float *)d_in[5];
    const float *b1 = (const float *)d_in[6];
    const float *w2 = (const float *)d_in[7];
    const float *b2 = (const float *)d_in[8];
    float *out = (float *)d_out;

    const int gcn_smem = (512 * 36 + 2048 + 64) * 4;   // 82176 B
    const int fc1_smem = (128 * 130 + 128 * 34) * 4;   // 83968 B
    cudaFuncSetAttribute(gcn_kernel, cudaFuncAttributeMaxDynamicSharedMemorySize, gcn_smem);
    cudaFuncSetAttribute(fc1_kernel, cudaFuncAttributeMaxDynamicSharedMemorySize, fc1_smem);

    conv_pool_kernel<<<dim3(16, 32), 256>>>(x, cw, cb);
    gcn_kernel<<<dim3(8, 32), 256, gcn_smem>>>(gw, gb);
    fc1_kernel<<<512, 128, fc1_smem>>>(w1);
    reduce_fc2_kernel<<<32, 1024>>>(b1, w2, b2, out);
}

// round 2
// speedup vs baseline: 1.2937x; 1.2937x over previous
#include <cuda_runtime.h>
#include <cstdint>

// ---------------------------------------------------------------------------
// PartBasedGraphCNN: conv3x3(3->32)+relu+pool2 -> grid-GCN(32->64) -> FC1 -> FC2
// fp32 throughout, packed f32x2 FMA. 5 kernels, __device__ scratch, no atomics.
// ---------------------------------------------------------------------------

#define K_FC 262144  // 4096 nodes * 64 feats

__device__ float d_pool_buf[32 * 32 * 64 * 64];     // [B][32][64][64]  16.8 MB
__device__ float d_g_buf[32u * 4096u * 64u];        // [B][N][64]       33.6 MB
__device__ float d_part_buf[592 * 32 * 128];        // [set][B][128]     9.7 MB
__device__ float d_f1_buf[32 * 128];                // [B][128]

__device__ __forceinline__ void fma2(float2 &d, const float2 a, const float2 b) {
    asm("fma.rn.f32x2 %0, %1, %2, %0;"
        : "+l"(*reinterpret_cast<unsigned long long *>(&d))
        : "l"(*reinterpret_cast<const unsigned long long *>(&a)),
          "l"(*reinterpret_cast<const unsigned long long *>(&b)));
}

__device__ __forceinline__ void cpa16(void *dst_smem, const void *src_gmem) {
    uint32_t d = (uint32_t)__cvta_generic_to_shared(dst_smem);
    asm volatile("cp.async.cg.shared.global [%0], [%1], 16;"
                 :: "r"(d), "l"(src_gmem));
}
#define CPA_COMMIT() asm volatile("cp.async.commit_group;")
#define CPA_WAIT(N)  asm volatile("cp.async.wait_group %0;" :: "n"(N))

// ---------------------------------------------------------------------------
// Kernel 1: conv 3x3 SAME + bias + relu + maxpool 2x2  (unchanged from R1)
// ---------------------------------------------------------------------------
__global__ void __launch_bounds__(256) conv_pool_kernel(
    const float *__restrict__ x, const float *__restrict__ cw,
    const float *__restrict__ cb)
{
    __shared__ float sin_[3][34][34];
    __shared__ float wp[27 * 32];
    __shared__ float bb[32];

    int t = threadIdx.x;
    int b = blockIdx.y;
    int tpy = (blockIdx.x >> 2) * 16, tpx = (blockIdx.x & 3) * 16;

    for (int i = t; i < 864; i += 256) {
        int co = i / 27, rem = i % 27;
        wp[rem * 32 + co] = cw[i];
    }
    if (t < 32) bb[t] = cb[t];

    int oy = 2 * tpy - 1, ox = 2 * tpx - 1;
    for (int i = t; i < 3 * 34 * 34; i += 256) {
        int ci = i / 1156, rem = i % 1156, iy = rem / 34, ix = rem % 34;
        int gy = oy + iy, gx = ox + ix;
        float v = 0.f;
        if (gy >= 0 && gy < 128 && gx >= 0 && gx < 128)
            v = x[((b * 3 + ci) * 128 + gy) * 128 + gx];
        sin_[ci][iy][ix] = v;
    }
    __syncthreads();

    int py = t >> 4, px = t & 15;
    float in[3][4][4];
#pragma unroll
    for (int ci = 0; ci < 3; ci++)
#pragma unroll
        for (int r = 0; r < 4; r++)
#pragma unroll
            for (int c = 0; c < 4; c++)
                in[ci][r][c] = sin_[ci][2 * py + r][2 * px + c];

    const float2 *wp2 = reinterpret_cast<const float2 *>(wp);
    int gy = tpy + py, gx = tpx + px;
    float *outb = d_pool_buf + (size_t)b * 131072;

#pragma unroll
    for (int g = 0; g < 4; g++) {
        float2 acc[2][2][4];
#pragma unroll
        for (int dy = 0; dy < 2; dy++)
#pragma unroll
            for (int dx = 0; dx < 2; dx++)
#pragma unroll
                for (int p = 0; p < 4; p++) acc[dy][dx][p] = make_float2(0.f, 0.f);

#pragma unroll
        for (int ci = 0; ci < 3; ci++)
#pragma unroll
            for (int ky = 0; ky < 3; ky++)
#pragma unroll
                for (int kx = 0; kx < 3; kx++) {
                    int tap = ci * 9 + ky * 3 + kx;
                    float2 w0 = wp2[tap * 16 + g * 4 + 0];
                    float2 w1 = wp2[tap * 16 + g * 4 + 1];
                    float2 w2 = wp2[tap * 16 + g * 4 + 2];
                    float2 w3 = wp2[tap * 16 + g * 4 + 3];
#pragma unroll
                    for (int dy = 0; dy < 2; dy++)
#pragma unroll
                        for (int dx = 0; dx < 2; dx++) {
                            float iv = in[ci][dy + ky][dx + kx];
                            float2 iv2 = make_float2(iv, iv);
                            fma2(acc[dy][dx][0], iv2, w0);
                            fma2(acc[dy][dx][1], iv2, w1);
                            fma2(acc[dy][dx][2], iv2, w2);
                            fma2(acc[dy][dx][3], iv2, w3);
                        }
                }
#pragma unroll
        for (int p = 0; p < 4; p++) {
            int co = g * 8 + p * 2;
            float mx = fmaxf(fmaxf(acc[0][0][p].x, acc[0][1][p].x),
                             fmaxf(acc[1][0][p].x, acc[1][1][p].x));
            float my = fmaxf(fmaxf(acc[0][0][p].y, acc[0][1][p].y),
                             fmaxf(acc[1][0][p].y, acc[1][1][p].y));
            mx = fmaxf(mx + bb[co], 0.f);
            my = fmaxf(my + bb[co + 1], 0.f);
            outb[(co * 64 + gy) * 64 + gx] = mx;
            outb[((co + 1) * 64 + gy) * 64 + gx] = my;
        }
    }
}

// ---------------------------------------------------------------------------
// Kernel 2: GCN (stencil on 32-dim feats, then x32->64 GEMM)  (unchanged)
// ---------------------------------------------------------------------------
__device__ __forceinline__ float dinvf(int r, int c) {
    int deg = 1 + (r > 0) + (r < 63) + (c > 0) + (c < 63);
    return rsqrtf((float)deg);
}

__global__ void __launch_bounds__(256) gcn_kernel(
    const float *__restrict__ gw, const float *__restrict__ gb)
{
    extern __shared__ float sm[];
    float *aggx = sm;            // [512][36]
    float *wg = sm + 512 * 36;   // [32][64]
    float *bg = wg + 2048;       // [64]

    int t = threadIdx.x, b = blockIdx.y;
    int node0 = blockIdx.x * 512;

    for (int i = t; i < 2048; i += 256) wg[i] = gw[i];
    if (t < 64) bg[t] = gb[t];

    const float *nf = d_pool_buf + (size_t)b * 131072;
    int q = t & 7, ns = t >> 3;
#pragma unroll 4
    for (int i = 0; i < 16; i++) {
        int nl = ns + 32 * i;
        int n = node0 + nl;
        int r = n >> 6, c = n & 63;
        float dn = dinvf(r, c);
        const float4 *base = reinterpret_cast<const float4 *>(nf) + n * 8 + q;
        float4 v = __ldg(base);
        float4 a;
        a.x = dn * v.x; a.y = dn * v.y; a.z = dn * v.z; a.w = dn * v.w;
        if (r > 0) {
            float s = dinvf(r - 1, c); float4 u = __ldg(base - 512);
            a.x += s * u.x; a.y += s * u.y; a.z += s * u.z; a.w += s * u.w;
        }
        if (r < 63) {
            float s = dinvf(r + 1, c); float4 u = __ldg(base + 512);
            a.x += s * u.x; a.y += s * u.y; a.z += s * u.z; a.w += s * u.w;
        }
        if (c > 0) {
            float s = dinvf(r, c - 1); float4 u = __ldg(base - 8);
            a.x += s * u.x; a.y += s * u.y; a.z += s * u.z; a.w += s * u.w;
        }
        if (c < 63) {
            float s = dinvf(r, c + 1); float4 u = __ldg(base + 8);
            a.x += s * u.x; a.y += s * u.y; a.z += s * u.z; a.w += s * u.w;
        }
        a.x *= dn; a.y *= dn; a.z *= dn; a.w *= dn;
        *reinterpret_cast<float4 *>(&aggx[nl * 36 + q * 4]) = a;
    }
    __syncthreads();

    int ot = t & 7, ng = t >> 3;
    const float4 *wg4 = reinterpret_cast<const float4 *>(wg);
    float *gout = d_g_buf + (size_t)b * 262144;
#pragma unroll
    for (int it = 0; it < 2; it++) {
        int nb = (it * 32 + ng) * 8;
        float2 acc[8][4];
#pragma unroll
        for (int i = 0; i < 8; i++)
#pragma unroll
            for (int p = 0; p < 4; p++) acc[i][p] = make_float2(0.f, 0.f);

#pragma unroll 4
        for (int f = 0; f < 32; f++) {
            float4 wA = wg4[f * 16 + ot * 2];
            float4 wB = wg4[f * 16 + ot * 2 + 1];
            float2 p0 = make_float2(wA.x, wA.y), p1 = make_float2(wA.z, wA.w);
            float2 p2 = make_float2(wB.x, wB.y), p3 = make_float2(wB.z, wB.w);
#pragma unroll
            for (int i = 0; i < 8; i++) {
                float av = aggx[(nb + i) * 36 + f];
                float2 ad = make_float2(av, av);
                fma2(acc[i][0], ad, p0);
                fma2(acc[i][1], ad, p1);
                fma2(acc[i][2], ad, p2);
                fma2(acc[i][3], ad, p3);
            }
        }
#pragma unroll
        for (int i = 0; i < 8; i++) {
            float2 *op = reinterpret_cast<float2 *>(
                gout + (size_t)(node0 + nb + i) * 64 + ot * 8);
#pragma unroll
            for (int p = 0; p < 4; p++) {
                float2 v;
                v.x = fmaxf(acc[i][p].x + bg[ot * 8 + 2 * p], 0.f);
                v.y = fmaxf(acc[i][p].y + bg[ot * 8 + 2 * p + 1], 0.f);
                op[p] = v;
            }
        }
    }
}

// ---------------------------------------------------------------------------
// Kernel 3: FC1. 296 persistent blocks (1 wave), cp.async double-buffered
// stages of 64 k. [row][k] smem, XOR-swizzled, fma2 accumulates over k-pairs.
// Thread tile: 8 j x 8 b. 2-way k-interleave within block -> 592 partial sets.
// ---------------------------------------------------------------------------
#define FC1_W_F4 (128 * 17)  // W buffer: 128 rows x 17 float4
#define FC1_G_F4 (32 * 17)   // G buffer:  32 rows x 17 float4

__device__ __forceinline__ int swz(int row) { return ((row >> 3) ^ row) & 7; }

__device__ __forceinline__ void fc1_load_stage(
    float4 *Wb, float4 *Gb, const float *__restrict__ w1,
    const float *__restrict__ g, int kglob, int t)
{
#pragma unroll
    for (int i = 0; i < 16; i++) {  // W: 128 rows x 16 float4
        int idx = i * 128 + t;
        int row = idx >> 4, kq = idx & 15;
        cpa16(&Wb[row * 17 + (kq ^ swz(row))],
              w1 + (size_t)row * K_FC + kglob + kq * 4);
    }
#pragma unroll
    for (int i = 0; i < 4; i++) {   // G: 32 rows x 16 float4
        int idx = i * 128 + t;
        int row = idx >> 4, kq = idx & 15;
        cpa16(&Gb[row * 17 + (kq ^ swz(row))],
              g + (size_t)row * K_FC + kglob + kq * 4);
    }
    CPA_COMMIT();
}

__global__ void __launch_bounds__(128, 2) fc1_kernel(const float *__restrict__ w1)
{
    extern __shared__ float4 sm4[];
    float4 *Wbuf[2] = {sm4, sm4 + FC1_W_F4};
    float4 *Gbuf[2] = {sm4 + 2 * FC1_W_F4, sm4 + 2 * FC1_W_F4 + FC1_G_F4};

    const float *g = d_g_buf;
    int t = threadIdx.x;
    int bg = t & 3, jg = (t >> 2) & 15, s = t >> 6;
    int j0 = jg * 8, b0 = bg * 8;

    int bi = blockIdx.x;
    int kstart, nst;
    if (bi < 272) { kstart = bi * 896; nst = 14; }
    else          { kstart = 272 * 896 + (bi - 272) * 768; nst = 12; }

    int wrow[8], wsz[8], grow[8], gsz[8];
#pragma unroll
    for (int i = 0; i < 8; i++) {
        wrow[i] = (j0 + i) * 17; wsz[i] = swz(j0 + i);
        grow[i] = (b0 + i) * 17; gsz[i] = swz(b0 + i);
    }

    float2 acc[8][8];
#pragma unroll
    for (int jj = 0; jj < 8; jj++)
#pragma unroll
        for (int bb = 0; bb < 8; bb++) acc[jj][bb] = make_float2(0.f, 0.f);

    fc1_load_stage(Wbuf[0], Gbuf[0], w1, g, kstart, t);

    for (int st = 0; st < nst; st++) {
        if (st + 1 < nst) {
            fc1_load_stage(Wbuf[(st + 1) & 1], Gbuf[(st + 1) & 1], w1, g,
                           kstart + (st + 1) * 64, t);
            CPA_WAIT(1);
        } else {
            CPA_WAIT(0);
        }
        __syncthreads();

        const float4 *Wb = Wbuf[st & 1];
        const float4 *Gb = Gbuf[st & 1];
#pragma unroll
        for (int u = 0; u < 8; u++) {
            int kq = 2 * u + s;
            float4 G4[8];
#pragma unroll
            for (int bb = 0; bb < 8; bb++) G4[bb] = Gb[grow[bb] + (kq ^ gsz[bb])];
#pragma unroll
            for (int jj = 0; jj < 8; jj++) {
                float4 w = Wb[wrow[jj] + (kq ^ wsz[jj])];
                float2 wl = make_float2(w.x, w.y), wh = make_float2(w.z, w.w);
#pragma unroll
                for (int bb = 0; bb < 8; bb++)
                    fma2(acc[jj][bb], make_float2(G4[bb].x, G4[bb].y), wl);
#pragma unroll
                for (int bb = 0; bb < 8; bb++)
                    fma2(acc[jj][bb], make_float2(G4[bb].z, G4[bb].w), wh);
            }
        }
        __syncthreads();
    }

    float *pp = d_part_buf + ((size_t)bi * 2 + s) * 4096;
#pragma unroll
    for (int bb = 0; bb < 8; bb++)
#pragma unroll
        for (int jj = 0; jj < 8; jj++)
            pp[(b0 + bb) * 128 + j0 + jj] = acc[jj][bb].x + acc[jj][bb].y;
}

// ---------------------------------------------------------------------------
// Kernel 4a: reduce 592 partial sets -> relu(f1 + b1).  grid (32 b, 4 jq)
// ---------------------------------------------------------------------------
__global__ void __launch_bounds__(256) fc1_reduce_kernel(const float *__restrict__ f1b)
{
    __shared__ float red[8][33];
    int t = threadIdx.x, b = blockIdx.x, jq = blockIdx.y;
    int jl = t & 31, sg = t >> 5;
    int j = jq * 32 + jl;

    const float *pp = d_part_buf + b * 128 + j;
    float ssum = 0.f;
#pragma unroll 8
    for (int i = sg; i < 592; i += 8) ssum += pp[(size_t)i * 4096];
    red[sg][jl] = ssum;
    __syncthreads();

    if (t < 32) {
        float v = red[0][t];
#pragma unroll
        for (int u = 1; u < 8; u++) v += red[u][t];
        int jo = jq * 32 + t;
        d_f1_buf[b * 128 + jo] = fmaxf(v + f1b[jo], 0.f);
    }
}

// ---------------------------------------------------------------------------
// Kernel 4b: FC2 (101 x 128) + bias.  grid 32 (one block per batch)
// ---------------------------------------------------------------------------
__global__ void __launch_bounds__(128) fc2_kernel(
    const float *__restrict__ w2, const float *__restrict__ b2,
    float *__restrict__ out)
{
    __shared__ float f1s[128];
    int t = threadIdx.x, b = blockIdx.x;
    f1s[t] = d_f1_buf[b * 128 + t];
    __syncthreads();

    if (t < 101) {
        float acc = b2[t];
        const float *wr = w2 + t * 128;
#pragma unroll 8
        for (int jj = 0; jj < 128; jj++) acc = fmaf(f1s[jj], __ldg(&wr[jj]), acc);
        out[b * 101 + t] = acc;
    }
}

// ---------------------------------------------------------------------------
extern "C" void kernel_launch(void *const *d_in, const int *in_sizes, int n_in,
                              void *d_out, int out_size)
{
    (void)in_sizes; (void)n_in; (void)out_size;
    const float *x  = (const float *)d_in[0];
    const float *cw = (const float *)d_in[1];
    const float *cb = (const float *)d_in[2];
    const float *gw = (const float *)d_in[3];
    const float *gb = (const float *)d_in[4];
    const float *w1 = (const float *)d_in[5];
    const float *b1 = (const float *)d_in[6];
    const float *w2 = (const float *)d_in[7];
    const float *b2 = (const float *)d_in[8];
    float *out = (float *)d_out;

    const int gcn_smem = (512 * 36 + 2048 + 64) * 4;          // 82176 B
    const int fc1_smem = (2 * FC1_W_F4 + 2 * FC1_G_F4) * 16;  // 87040 B
    cudaFuncSetAttribute(gcn_kernel, cudaFuncAttributeMaxDynamicSharedMemorySize, gcn_smem);
    cudaFuncSetAttribute(fc1_kernel, cudaFuncAttributeMaxDynamicSharedMemorySize, fc1_smem);

    conv_pool_kernel<<<dim3(16, 32), 256>>>(x, cw, cb);
    gcn_kernel<<<dim3(8, 32), 256, gcn_smem>>>(gw, gb);
    fc1_kernel<<<296, 128, fc1_smem>>>(w1);
    fc1_reduce_kernel<<<dim3(32, 4), 256>>>(b1);
    fc2_kernel<<<32, 128>>>(w2, b2, out);
}